// round 11
// baseline (speedup 1.0000x reference)
#include <cuda_runtime.h>

// ---------------------------------------------------------------------------
// B=4, N=256, E=64, C=128, H=256.
// out[b,n,m] = W3.relu(W2.relu(W1.concat(edge,row,col)+b1)+b2)+b3
// R[b,n,h] = W1r.node[:,n] + b1 ; C[b,m,h] = W1c.node[:,m]
// Single-pass TF32 mma.sync (m16n8k8). This round: 512 threads (16 warps,
// 4/SMSP) for latency hiding; smem cross-warp output reduction; 2 prep
// launches so ncu -s5 captures the main kernel.
// ---------------------------------------------------------------------------

__device__ float g_W1rT[128 * 256];
__device__ float g_W1cT[128 * 256];
__device__ float g_R[4 * 256 * 256];          // + b1 folded
__device__ float g_C[4 * 256 * 256];
__device__ float2 g_W1i[256 * 32];            // W1e tf32, [h][kc][t4] pairs (k,k+4)
__device__ float g_W2t[256 * 256];            // W2 tf32, row-major [h][k]

// ---------------- helpers --------------------------------------------------
__device__ __forceinline__ float tf32r(float v) {
    unsigned u;
    asm("cvt.rna.tf32.f32 %0, %1;" : "=r"(u) : "f"(v));
    return __uint_as_float(u);
}
__device__ __forceinline__ void mma_tf32(float d[4], float a0, float a1,
                                         float a2, float a3, float b0, float b1) {
    asm volatile(
        "mma.sync.aligned.m16n8k8.row.col.f32.tf32.tf32.f32 "
        "{%0,%1,%2,%3}, {%4,%5,%6,%7}, {%8,%9}, {%0,%1,%2,%3};"
        : "+f"(d[0]), "+f"(d[1]), "+f"(d[2]), "+f"(d[3])
        : "r"(__float_as_uint(a0)), "r"(__float_as_uint(a1)),
          "r"(__float_as_uint(a2)), "r"(__float_as_uint(a3)),
          "r"(__float_as_uint(b0)), "r"(__float_as_uint(b1)));
}
#define IOFF(k) ((((k) >> 3) << 5) + (((k) & 3) << 3) + ((((k) >> 2) & 1) << 2))

// ---------------- prep kernels (2 launches total) --------------------------
__global__ void prep_all(const float* __restrict__ W1, const float* __restrict__ W2,
                         const float* __restrict__ b3, float* __restrict__ out) {
    int i = blockIdx.x * 256 + threadIdx.x;   // 262144
    out[i] = b3[0];
    if (i < 65536) g_W2t[i] = tf32r(W2[i]);
    if (i < 32768) {
        int c = i >> 8, h = i & 255;
        g_W1rT[i] = W1[h * 320 + 64 + c];
        g_W1cT[i] = W1[h * 320 + 192 + c];
    }
    if (i < 8192) {
        int h = i >> 5, kc = (i >> 2) & 7, t4 = i & 3;
        int k = kc * 8 + t4;
        g_W1i[i] = make_float2(tf32r(W1[h * 320 + k]), tf32r(W1[h * 320 + k + 4]));
    }
}
__global__ void prep_np(const float* __restrict__ node, const float* __restrict__ b1) {
    int b = blockIdx.x >> 8, p = blockIdx.x & 255;
    int h = threadIdx.x;
    __shared__ float ns[128];
    if (h < 128) ns[h] = node[(b * 128 + h) * 256 + p];
    __syncthreads();
    float r = 0.f, c = 0.f;
#pragma unroll 16
    for (int k = 0; k < 128; k++) {
        float v = ns[k];
        r = fmaf(g_W1rT[k * 256 + h], v, r);
        c = fmaf(g_W1cT[k * 256 + h], v, c);
    }
    int o = (b * 256 + p) * 256 + h;
    g_R[o] = r + b1[h];
    g_C[o] = c;
}

// ---------------- main kernel ----------------------------------------------
#define PA 304                      // A row pitch (bytes): 76 words, mod32=12
#define PH 1072                     // h1/W2 row pitch (bytes): 268 words, mod32=12
#define SW2   0                     // 128 h' rows x PH
#define SA1   137216                // 64 px rows x PA
#define SH1   156672                // 64 px rows x PH
#define SW3   225280                // 128 f32
#define SB2   225792                // 128 f32
#define SRED  226304                // 16 warps x 64 px f32
#define SMEM_TOTAL 230400

__global__ __launch_bounds__(512, 1)
void mlp_mma(const float* __restrict__ edge, const float* __restrict__ b2,
             const float* __restrict__ W3, float* __restrict__ out) {
    extern __shared__ char smem[];
    const int tid = threadIdx.x;
    const int wid = tid >> 5, lane = tid & 31;
    const int g = lane >> 2, t4 = lane & 3;
    const int hh = blockIdx.x & 1;

    // stage W2 half (tf32, interleaved) + W3/b2 halves
    for (int i = tid; i < 4096; i += 512) {       // i = h'(7b)*32 + kc(5b)
        int hp = i >> 5, kc = i & 31;
        const float4* src = (const float4*)(g_W2t + (hh * 128 + hp) * 256 + kc * 8);
        float4 x = src[0], y = src[1];
        float4* dst = (float4*)(smem + SW2 + hp * PH + kc * 32);
        dst[0] = make_float4(x.x, y.x, x.y, y.y);
        dst[1] = make_float4(x.z, y.z, x.w, y.w);
    }
    if (tid < 128) {
        ((float*)(smem + SW3))[tid] = W3[hh * 128 + tid];
        ((float*)(smem + SB2))[tid] = b2[hh * 128 + tid];
    }

    const float* w3s = (const float*)(smem + SW3);
    const float* b2s = (const float*)(smem + SB2);
    float* red = (float*)(smem + SRED);
    const int hb1 = wid * 16;   // GEMM1: 16 h per warp (ni=2)
    const int hb2 = wid * 8;    // GEMM2: 8 h' per warp
    const int spx = tid & 63, se = tid >> 6;      // staging: 8 e-chunks of 8

    // prologue: stage first edge tile
    {
        int t0 = blockIdx.x >> 1;
        int mt = t0 & 3, n = (t0 >> 2) & 255, b = t0 >> 10;
        const float* ep = edge +
            ((size_t)(b * 64 + se * 8) * 256 + n) * 256 + mt * 64 + spx;
        float v[8];
#pragma unroll
        for (int j = 0; j < 8; j++) v[j] = tf32r(ep[(size_t)j * 65536]);
        float4* dst = (float4*)(smem + SA1 + spx * PA + se * 32);
        dst[0] = make_float4(v[0], v[4], v[1], v[5]);
        dst[1] = make_float4(v[2], v[6], v[3], v[7]);
    }
    __syncthreads();

    for (int t = blockIdx.x >> 1; t < 4096; t += 74) {
        const int mt = t & 3, n = (t >> 2) & 255, b = t >> 10;
        const int m0 = mt * 64;

        float2 Rv[2];
        {
            const float* Rb = g_R + ((b * 256 + n) << 8);
#pragma unroll
            for (int ni = 0; ni < 2; ni++)
                Rv[ni] = *(const float2*)(Rb + hb1 + ni * 8 + 2 * t4);
        }

        // ---- GEMM1: D1[64px, 16h/warp] = A1 x W1e^T, K=64 ----
        float acc1[4][2][4];
#pragma unroll
        for (int mi = 0; mi < 4; mi++)
#pragma unroll
            for (int ni = 0; ni < 2; ni++)
#pragma unroll
                for (int q = 0; q < 4; q++) acc1[mi][ni][q] = 0.f;

#pragma unroll
        for (int kc = 0; kc < 8; kc++) {
            float2 p0[4], p1[4];
#pragma unroll
            for (int mi = 0; mi < 4; mi++) {
                p0[mi] = *(float2*)(smem + SA1 + (mi * 16 + g) * PA + kc * 32 + t4 * 8);
                p1[mi] = *(float2*)(smem + SA1 + (mi * 16 + g + 8) * PA + kc * 32 + t4 * 8);
            }
            float2 b0 = g_W1i[(hb1 + g) * 32 + kc * 4 + t4];
            float2 b1 = g_W1i[(hb1 + 8 + g) * 32 + kc * 4 + t4];
#pragma unroll
            for (int mi = 0; mi < 4; mi++) {
                mma_tf32(acc1[mi][0], p0[mi].x, p1[mi].x, p0[mi].y, p1[mi].y, b0.x, b0.y);
                mma_tf32(acc1[mi][1], p0[mi].x, p1[mi].x, p0[mi].y, p1[mi].y, b1.x, b1.y);
            }
        }

        // ---- epilogue 1: relu(D1 + R + C) -> h1 (tf32) in SMEM ----
        {
            const float* Cb = g_C + ((size_t)(b * 256 + m0) << 8);
#pragma unroll
            for (int mi = 0; mi < 4; mi++)
#pragma unroll
                for (int ni = 0; ni < 2; ni++) {
                    int h = hb1 + ni * 8 + 2 * t4;
                    int px0 = mi * 16 + g, px1 = px0 + 8;
                    float2 C0 = *(const float2*)(Cb + (px0 << 8) + h);
                    float2 C1 = *(const float2*)(Cb + (px1 << 8) + h);
                    float v00 = fmaxf(acc1[mi][ni][0] + Rv[ni].x + C0.x, 0.f);
                    float v01 = fmaxf(acc1[mi][ni][1] + Rv[ni].y + C0.y, 0.f);
                    float v10 = fmaxf(acc1[mi][ni][2] + Rv[ni].x + C1.x, 0.f);
                    float v11 = fmaxf(acc1[mi][ni][3] + Rv[ni].y + C1.y, 0.f);
                    unsigned o0 = SH1 + px0 * PH, o1 = SH1 + px1 * PH;
                    unsigned kh = IOFF(h), kh1 = IOFF(h + 1);
                    *(float*)(smem + o0 + kh)  = tf32r(v00);
                    *(float*)(smem + o0 + kh1) = tf32r(v01);
                    *(float*)(smem + o1 + kh)  = tf32r(v10);
                    *(float*)(smem + o1 + kh1) = tf32r(v11);
                }
        }
        __syncthreads();   // h1 visible; A tile free for re-staging

        // ---- prefetch next tile's edge into registers ----
        float ev[8];
        const int tn = t + 74;
        if (tn < 4096) {
            int mtn = tn & 3, nn = (tn >> 2) & 255, bn = tn >> 10;
            const float* ep = edge +
                ((size_t)(bn * 64 + se * 8) * 256 + nn) * 256 + mtn * 64 + spx;
#pragma unroll
            for (int j = 0; j < 8; j++) ev[j] = ep[(size_t)j * 65536];
        }

        // ---- GEMM2: D2[64px, 8h'/warp] = h1 x W2half^T, K=256 ----
        float acc2[4][4];
#pragma unroll
        for (int mi = 0; mi < 4; mi++)
#pragma unroll
            for (int q = 0; q < 4; q++) acc2[mi][q] = 0.f;

#pragma unroll 4
        for (int kc = 0; kc < 32; kc++) {
            float2 p0[4], p1[4];
#pragma unroll
            for (int mi = 0; mi < 4; mi++) {
                p0[mi] = *(float2*)(smem + SH1 + (mi * 16 + g) * PH + kc * 32 + t4 * 8);
                p1[mi] = *(float2*)(smem + SH1 + (mi * 16 + g + 8) * PH + kc * 32 + t4 * 8);
            }
            float2 wb = *(float2*)(smem + SW2 + (hb2 + g) * PH + kc * 32 + t4 * 8);
#pragma unroll
            for (int mi = 0; mi < 4; mi++)
                mma_tf32(acc2[mi], p0[mi].x, p1[mi].x, p0[mi].y, p1[mi].y,
                         wb.x, wb.y);
        }

        // ---- epilogue 2 + layer 3: per-warp partials -> smem reduce ----
        {
            int h = hb2 + 2 * t4;
            float w3a = w3s[h], w3b = w3s[h + 1];
            float ba = b2s[h], bbv = b2s[h + 1];
            float po[4][2];
#pragma unroll
            for (int mi = 0; mi < 4; mi++) {
                po[mi][0] = fmaf(w3a, fmaxf(acc2[mi][0] + ba, 0.f),
                            fmaf(w3b, fmaxf(acc2[mi][1] + bbv, 0.f), 0.f));
                po[mi][1] = fmaf(w3a, fmaxf(acc2[mi][2] + ba, 0.f),
                            fmaf(w3b, fmaxf(acc2[mi][3] + bbv, 0.f), 0.f));
#pragma unroll
                for (int r = 0; r < 2; r++) {
                    po[mi][r] += __shfl_xor_sync(0xffffffffu, po[mi][r], 1);
                    po[mi][r] += __shfl_xor_sync(0xffffffffu, po[mi][r], 2);
                }
            }
            if (t4 == 0) {
#pragma unroll
                for (int mi = 0; mi < 4; mi++) {
                    red[wid * 64 + mi * 16 + g] = po[mi][0];
                    red[wid * 64 + mi * 16 + g + 8] = po[mi][1];
                }
            }
        }
        __syncthreads();

        // ---- store prefetched edge into the (now free) A buffer ----
        if (tn < 4096) {
            float4* dst = (float4*)(smem + SA1 + spx * PA + se * 32);
            dst[0] = make_float4(tf32r(ev[0]), tf32r(ev[4]), tf32r(ev[1]), tf32r(ev[5]));
            dst[1] = make_float4(tf32r(ev[2]), tf32r(ev[6]), tf32r(ev[3]), tf32r(ev[7]));
        }

        // ---- cross-warp output reduction: one atomicAdd per pixel ----
        if (tid < 64) {
            float s = 0.f;
#pragma unroll
            for (int w = 0; w < 16; w++) s += red[w * 64 + tid];
            atomicAdd(out + ((b * 256 + n) << 8) + m0 + tid, s);
        }
        __syncthreads();
    }
}

extern "C" void kernel_launch(void* const* d_in, const int* in_sizes, int n_in,
                              void* d_out, int out_size) {
    const float* edge = (const float*)d_in[0];
    const float* node = (const float*)d_in[1];
    const float* W1   = (const float*)d_in[2];
    const float* b1   = (const float*)d_in[3];
    const float* W2   = (const float*)d_in[4];
    const float* b2   = (const float*)d_in[5];
    const float* W3   = (const float*)d_in[6];
    const float* b3   = (const float*)d_in[7];
    float* out = (float*)d_out;

    cudaFuncSetAttribute(mlp_mma, cudaFuncAttributeMaxDynamicSharedMemorySize,
                         SMEM_TOTAL);

    prep_all<<<1024, 256>>>(W1, W2, b3, out);
    prep_np<<<1024, 256>>>(node, b1);
    mlp_mma<<<148, 512, SMEM_TOTAL>>>(edge, b2, W3, out);
}

// round 13
// speedup vs baseline: 2.9983x; 2.9983x over previous
#include <cuda_runtime.h>
#include <cuda_fp16.h>

// ---------------------------------------------------------------------------
// B=4, N=256, E=64, C=128, H=256.
// out[b,n,m] = W3.relu(W2.relu(W1.concat(edge,row,col)+b1)+b2)+b3
// R[b,n,h] = W1r.node[:,n] + b1 ; C[b,m,h] = W1c.node[:,m]
// fp16 m16n8k16 mma (same 10-bit mantissa as tf32, half the mma count and
// half the LDS traffic). K-interleaved half-pair layout; 256 thr, M=64 tiles.
// ---------------------------------------------------------------------------

__device__ float g_W1rT[128 * 256];
__device__ float g_W1cT[128 * 256];
__device__ float g_R[4 * 256 * 256];          // + b1 folded
__device__ float g_C[4 * 256 * 256];
__device__ uint2 g_W1p[256 * 16];             // W1e fp16 B-frags [h][kc4][t4]
__device__ __half g_W2h[256 * 256];           // W2 fp16, k-interleaved per 16-block

__constant__ int c_perm16[16] = {0,1,8,9,2,3,10,11,4,5,12,13,6,7,14,15};

// ---------------- helpers --------------------------------------------------
__device__ __forceinline__ void mma_f16(float d[4], unsigned a0, unsigned a1,
                                        unsigned a2, unsigned a3,
                                        unsigned b0, unsigned b1) {
    asm volatile(
        "mma.sync.aligned.m16n8k16.row.col.f32.f16.f16.f32 "
        "{%0,%1,%2,%3}, {%4,%5,%6,%7}, {%8,%9}, {%0,%1,%2,%3};"
        : "+f"(d[0]), "+f"(d[1]), "+f"(d[2]), "+f"(d[3])
        : "r"(a0), "r"(a1), "r"(a2), "r"(a3), "r"(b0), "r"(b1));
}
__device__ __forceinline__ unsigned h2pack(float x, float y) {
    __half2 h = __floats2half2_rn(x, y);
    return *(unsigned*)&h;
}

// ---------------- prep kernels (2 launches) --------------------------------
__global__ void prep_all(const float* __restrict__ W1, const float* __restrict__ W2,
                         const float* __restrict__ b3, float* __restrict__ out) {
    int i = blockIdx.x * 256 + threadIdx.x;   // 262144
    out[i] = b3[0];
    if (i < 65536) {                           // g_W2h, interleaved
        int h = i >> 8, kk = i & 255;
        int kcb = kk >> 4, j = kk & 15;
        g_W2h[i] = __float2half_rn(W2[h * 256 + kcb * 16 + c_perm16[j]]);
    }
    if (i < 32768) {
        int c = i >> 8, h = i & 255;
        g_W1rT[i] = W1[h * 320 + 64 + c];
        g_W1cT[i] = W1[h * 320 + 192 + c];
    }
    if (i < 4096) {                            // g_W1p B-frags
        int h = i >> 4, r = i & 15;
        int kc = r >> 2, t4 = r & 3, ks = kc * 16 + 2 * t4;
        uint2 v;
        v.x = h2pack(W1[h * 320 + ks], W1[h * 320 + ks + 1]);
        v.y = h2pack(W1[h * 320 + ks + 8], W1[h * 320 + ks + 9]);
        g_W1p[i] = v;
    }
}
__global__ void prep_np(const float* __restrict__ node, const float* __restrict__ b1) {
    int b = blockIdx.x >> 8, p = blockIdx.x & 255;
    int h = threadIdx.x;
    __shared__ float ns[128];
    if (h < 128) ns[h] = node[(b * 128 + h) * 256 + p];
    __syncthreads();
    float r = 0.f, c = 0.f;
#pragma unroll 16
    for (int k = 0; k < 128; k++) {
        float v = ns[k];
        r = fmaf(g_W1rT[k * 256 + h], v, r);
        c = fmaf(g_W1cT[k * 256 + h], v, c);
    }
    int o = (b * 256 + p) * 256 + h;
    g_R[o] = r + b1[h];
    g_C[o] = c;
}

// ---------------- main kernel ----------------------------------------------
#define PA 160                      // A row pitch (bytes): 40w, mod32=8
#define PH 544                      // h1/W2 row pitch (bytes): 136w, mod32=8
#define SW2   0                     // 128 rows x PH = 69632
#define SA1   69632                 // 64 rows x PA = 10240
#define SH1   79872                 // 64 rows x PH = 34816
#define SW3   114688                // 128 f32
#define SB2   115200                // 128 f32
#define SMEM_TOTAL 115712

__global__ __launch_bounds__(256, 1)
void mlp_mma(const float* __restrict__ edge, const float* __restrict__ b2,
             const float* __restrict__ W3, float* __restrict__ out) {
    extern __shared__ char smem[];
    const int tid = threadIdx.x;
    const int wid = tid >> 5, lane = tid & 31;
    const int g = lane >> 2, t4 = lane & 3;
    const int hh = blockIdx.x & 1;

    // stage W2 half (fp16 interleaved rows) + W3/b2 halves
    for (int i = tid; i < 4096; i += 256) {        // hp(7b) * 32 + c(5b)
        int hp = i >> 5, c = i & 31;
        *(uint4*)(smem + SW2 + hp * PH + c * 16) =
            ((const uint4*)(g_W2h + (hh * 128 + hp) * 256))[c];
    }
    if (tid < 128) {
        ((float*)(smem + SW3))[tid] = W3[hh * 128 + tid];
        ((float*)(smem + SB2))[tid] = b2[hh * 128 + tid];
    }

    const float* w3s = (const float*)(smem + SW3);
    const float* b2s = (const float*)(smem + SB2);
    const int hb1 = wid * 32;   // GEMM1: 32 h per warp (ni=4)
    const int hb2 = wid * 16;   // GEMM2: 16 h' per warp (ni=2)
    const int spx = tid & 63, sq = tid >> 6;       // staging: 4 e-blocks of 16

    // prologue: stage first edge tile (fp16, interleaved)
    {
        int t0 = blockIdx.x >> 1;
        int mt = t0 & 3, n = (t0 >> 2) & 255, b = t0 >> 10;
        const float* ep = edge +
            ((size_t)(b * 64 + sq * 16) * 256 + n) * 256 + mt * 64 + spx;
        float v[16];
#pragma unroll
        for (int j = 0; j < 16; j++) v[j] = ep[(size_t)j * 65536];
        unsigned w[8];
        w[0]=h2pack(v[0],v[1]);  w[1]=h2pack(v[8],v[9]);
        w[2]=h2pack(v[2],v[3]);  w[3]=h2pack(v[10],v[11]);
        w[4]=h2pack(v[4],v[5]);  w[5]=h2pack(v[12],v[13]);
        w[6]=h2pack(v[6],v[7]);  w[7]=h2pack(v[14],v[15]);
        uint4* dst = (uint4*)(smem + SA1 + spx * PA + sq * 32);
        dst[0] = make_uint4(w[0], w[1], w[2], w[3]);
        dst[1] = make_uint4(w[4], w[5], w[6], w[7]);
    }
    __syncthreads();

    for (int t = blockIdx.x >> 1; t < 4096; t += 74) {
        const int mt = t & 3, n = (t >> 2) & 255, b = t >> 10;
        const int m0 = mt * 64;

        float2 Rv[4];
        {
            const float* Rb = g_R + ((b * 256 + n) << 8);
#pragma unroll
            for (int ni = 0; ni < 4; ni++)
                Rv[ni] = *(const float2*)(Rb + hb1 + ni * 8 + 2 * t4);
        }

        // ---- GEMM1: D1[64px, 32h/warp] = A1 x W1e^T, K=64 (4 k16) ----
        float acc1[4][4][4];
#pragma unroll
        for (int mi = 0; mi < 4; mi++)
#pragma unroll
            for (int ni = 0; ni < 4; ni++)
#pragma unroll
                for (int q = 0; q < 4; q++) acc1[mi][ni][q] = 0.f;

#pragma unroll
        for (int kc = 0; kc < 4; kc++) {
            uint2 ar0[4], ar1[4];
#pragma unroll
            for (int mi = 0; mi < 4; mi++) {
                ar0[mi] = *(uint2*)(smem + SA1 + (mi * 16 + g) * PA + kc * 32 + t4 * 8);
                ar1[mi] = *(uint2*)(smem + SA1 + (mi * 16 + g + 8) * PA + kc * 32 + t4 * 8);
            }
#pragma unroll
            for (int ni = 0; ni < 4; ni++) {
                uint2 bb = g_W1p[(hb1 + ni * 8 + g) * 16 + kc * 4 + t4];
#pragma unroll
                for (int mi = 0; mi < 4; mi++)
                    mma_f16(acc1[mi][ni], ar0[mi].x, ar1[mi].x, ar0[mi].y, ar1[mi].y,
                            bb.x, bb.y);
            }
        }

        // ---- epilogue 1: relu(D1 + R + C) -> h1 (fp16, interleaved) ----
        {
            const float* Cb = g_C + ((size_t)(b * 256 + m0) << 8);
#pragma unroll
            for (int mi = 0; mi < 4; mi++)
#pragma unroll
                for (int ni = 0; ni < 4; ni++) {
                    int h = hb1 + ni * 8 + 2 * t4;
                    int px0 = mi * 16 + g, px1 = px0 + 8;
                    float2 C0 = *(const float2*)(Cb + (px0 << 8) + h);
                    float2 C1 = *(const float2*)(Cb + (px1 << 8) + h);
                    float v00 = fmaxf(acc1[mi][ni][0] + Rv[ni].x + C0.x, 0.f);
                    float v01 = fmaxf(acc1[mi][ni][1] + Rv[ni].y + C0.y, 0.f);
                    float v10 = fmaxf(acc1[mi][ni][2] + Rv[ni].x + C1.x, 0.f);
                    float v11 = fmaxf(acc1[mi][ni][3] + Rv[ni].y + C1.y, 0.f);
                    int kcb = h >> 4, p = (h >> 1) & 7;
                    int word = ((p & 3) << 1) | (p >> 2);
                    unsigned off = kcb * 32 + word * 4;
                    *(unsigned*)(smem + SH1 + px0 * PH + off) = h2pack(v00, v01);
                    *(unsigned*)(smem + SH1 + px1 * PH + off) = h2pack(v10, v11);
                }
        }
        __syncthreads();   // h1 visible; A tile free for re-staging

        // ---- prefetch next tile's edge into registers ----
        float ev[16];
        const int tn = t + 74;
        if (tn < 4096) {
            int mtn = tn & 3, nn = (tn >> 2) & 255, bn = tn >> 10;
            const float* ep = edge +
                ((size_t)(bn * 64 + sq * 16) * 256 + nn) * 256 + mtn * 64 + spx;
#pragma unroll
            for (int j = 0; j < 16; j++) ev[j] = ep[(size_t)j * 65536];
        }

        // ---- GEMM2: D2[64px, 16h'/warp] = h1 x W2half^T, K=256 (16 k16) ----
        float acc2[4][2][4];
#pragma unroll
        for (int mi = 0; mi < 4; mi++)
#pragma unroll
            for (int ni = 0; ni < 2; ni++)
#pragma unroll
                for (int q = 0; q < 4; q++) acc2[mi][ni][q] = 0.f;

#pragma unroll 4
        for (int kc = 0; kc < 16; kc++) {
            uint2 ar0[4], ar1[4];
#pragma unroll
            for (int mi = 0; mi < 4; mi++) {
                ar0[mi] = *(uint2*)(smem + SH1 + (mi * 16 + g) * PH + kc * 32 + t4 * 8);
                ar1[mi] = *(uint2*)(smem + SH1 + (mi * 16 + g + 8) * PH + kc * 32 + t4 * 8);
            }
#pragma unroll
            for (int ni = 0; ni < 2; ni++) {
                uint2 wb = *(uint2*)(smem + SW2 + (hb2 + ni * 8 + g) * PH + kc * 32 + t4 * 8);
#pragma unroll
                for (int mi = 0; mi < 4; mi++)
                    mma_f16(acc2[mi][ni], ar0[mi].x, ar1[mi].x, ar0[mi].y, ar1[mi].y,
                            wb.x, wb.y);
            }
        }

        // ---- epilogue 2 + layer 3 + atomic combine ----
        {
            float po[4][2];
#pragma unroll
            for (int mi = 0; mi < 4; mi++) { po[mi][0] = 0.f; po[mi][1] = 0.f; }
#pragma unroll
            for (int mi = 0; mi < 4; mi++)
#pragma unroll
                for (int ni = 0; ni < 2; ni++) {
                    int h = hb2 + ni * 8 + 2 * t4;
                    float w3a = w3s[h], w3b = w3s[h + 1];
                    float ba = b2s[h], bbv = b2s[h + 1];
                    po[mi][0] = fmaf(w3a, fmaxf(acc2[mi][ni][0] + ba, 0.f), po[mi][0]);
                    po[mi][0] = fmaf(w3b, fmaxf(acc2[mi][ni][1] + bbv, 0.f), po[mi][0]);
                    po[mi][1] = fmaf(w3a, fmaxf(acc2[mi][ni][2] + ba, 0.f), po[mi][1]);
                    po[mi][1] = fmaf(w3b, fmaxf(acc2[mi][ni][3] + bbv, 0.f), po[mi][1]);
                }
#pragma unroll
            for (int mi = 0; mi < 4; mi++)
#pragma unroll
                for (int r = 0; r < 2; r++) {
                    po[mi][r] += __shfl_xor_sync(0xffffffffu, po[mi][r], 1);
                    po[mi][r] += __shfl_xor_sync(0xffffffffu, po[mi][r], 2);
                }
            if (t4 == 0) {
                int ob = ((b * 256 + n) << 8) + m0;
#pragma unroll
                for (int mi = 0; mi < 4; mi++) {
                    atomicAdd(out + ob + mi * 16 + g, po[mi][0]);
                    atomicAdd(out + ob + mi * 16 + g + 8, po[mi][1]);
                }
            }
        }

        // ---- store prefetched edge into the (now free) A buffer ----
        if (tn < 4096) {
            unsigned w[8];
            w[0]=h2pack(ev[0],ev[1]);  w[1]=h2pack(ev[8],ev[9]);
            w[2]=h2pack(ev[2],ev[3]);  w[3]=h2pack(ev[10],ev[11]);
            w[4]=h2pack(ev[4],ev[5]);  w[5]=h2pack(ev[12],ev[13]);
            w[6]=h2pack(ev[6],ev[7]);  w[7]=h2pack(ev[14],ev[15]);
            uint4* dst = (uint4*)(smem + SA1 + spx * PA + sq * 32);
            dst[0] = make_uint4(w[0], w[1], w[2], w[3]);
            dst[1] = make_uint4(w[4], w[5], w[6], w[7]);
        }
        __syncthreads();
    }
}

extern "C" void kernel_launch(void* const* d_in, const int* in_sizes, int n_in,
                              void* d_out, int out_size) {
    const float* edge = (const float*)d_in[0];
    const float* node = (const float*)d_in[1];
    const float* W1   = (const float*)d_in[2];
    const float* b1   = (const float*)d_in[3];
    const float* W2   = (const float*)d_in[4];
    const float* b2   = (const float*)d_in[5];
    const float* W3   = (const float*)d_in[6];
    const float* b3   = (const float*)d_in[7];
    float* out = (float*)d_out;

    cudaFuncSetAttribute(mlp_mma, cudaFuncAttributeMaxDynamicSharedMemorySize,
                         SMEM_TOTAL);

    prep_all<<<1024, 256>>>(W1, W2, b3, out);
    prep_np<<<1024, 256>>>(node, b1);
    mlp_mma<<<148, 256, SMEM_TOTAL>>>(edge, b2, W3, out);
}

// round 16
// speedup vs baseline: 4.2971x; 1.4332x over previous
#include <cuda_runtime.h>
#include <cuda_fp16.h>

// ---------------------------------------------------------------------------
// B=4, N=256, E=64, C=128, H=256.
// out[b,n,m] = W3.relu(W2.relu(W1.concat(edge,row,col)+b1)+b2)+b3
// R[b,n,h] = W1r.node[:,n] + b1 ; C[b,m,h] = W1c.node[:,m]
// fp16 m16n8k16 mma. This round: full W2 (fp16, 128KB) in SMEM -> ONE CTA
// per tile (no hh duplication of GEMM1/edge/C), no output atomics.
// ---------------------------------------------------------------------------

__device__ float g_W1rT[128 * 256];
__device__ float g_W1cT[128 * 256];
__device__ float g_R[4 * 256 * 256];          // + b1 folded
__device__ float g_C[4 * 256 * 256];
__device__ uint2 g_W1p[256 * 16];             // W1e fp16 B-frags [h][kc4][t4]
__device__ __half g_W2h[256 * 256];           // W2 fp16, k-interleaved per 16-block

__constant__ int c_perm16[16] = {0,1,8,9,2,3,10,11,4,5,12,13,6,7,14,15};

// ---------------- helpers --------------------------------------------------
__device__ __forceinline__ void mma_f16(float d[4], unsigned a0, unsigned a1,
                                        unsigned a2, unsigned a3,
                                        unsigned b0, unsigned b1) {
    asm volatile(
        "mma.sync.aligned.m16n8k16.row.col.f32.f16.f16.f32 "
        "{%0,%1,%2,%3}, {%4,%5,%6,%7}, {%8,%9}, {%0,%1,%2,%3};"
        : "+f"(d[0]), "+f"(d[1]), "+f"(d[2]), "+f"(d[3])
        : "r"(a0), "r"(a1), "r"(a2), "r"(a3), "r"(b0), "r"(b1));
}
__device__ __forceinline__ unsigned h2pack(float x, float y) {
    __half2 h = __floats2half2_rn(x, y);
    return *(unsigned*)&h;
}

// ---------------- prep kernels (2 launches) --------------------------------
__global__ void prep_all(const float* __restrict__ W1, const float* __restrict__ W2) {
    int i = blockIdx.x * 256 + threadIdx.x;   // 65536
    {                                          // g_W2h, interleaved
        int h = i >> 8, kk = i & 255;
        int kcb = kk >> 4, j = kk & 15;
        g_W2h[i] = __float2half_rn(W2[h * 256 + kcb * 16 + c_perm16[j]]);
    }
    if (i < 32768) {
        int c = i >> 8, h = i & 255;
        g_W1rT[i] = W1[h * 320 + 64 + c];
        g_W1cT[i] = W1[h * 320 + 192 + c];
    }
    if (i < 4096) {                            // g_W1p B-frags
        int h = i >> 4, r = i & 15;
        int kc = r >> 2, t4 = r & 3, ks = kc * 16 + 2 * t4;
        uint2 v;
        v.x = h2pack(W1[h * 320 + ks], W1[h * 320 + ks + 1]);
        v.y = h2pack(W1[h * 320 + ks + 8], W1[h * 320 + ks + 9]);
        g_W1p[i] = v;
    }
}
__global__ void prep_np(const float* __restrict__ node, const float* __restrict__ b1) {
    int b = blockIdx.x >> 8, p = blockIdx.x & 255;
    int h = threadIdx.x;
    __shared__ float ns[128];
    if (h < 128) ns[h] = node[(b * 128 + h) * 256 + p];
    __syncthreads();
    float r = 0.f, c = 0.f;
#pragma unroll 16
    for (int k = 0; k < 128; k++) {
        float v = ns[k];
        r = fmaf(g_W1rT[k * 256 + h], v, r);
        c = fmaf(g_W1cT[k * 256 + h], v, c);
    }
    int o = (b * 256 + p) * 256 + h;
    g_R[o] = r + b1[h];
    g_C[o] = c;
}

// ---------------- main kernel ----------------------------------------------
#define PA 160                      // A row pitch (bytes): 40w, mod32=8
#define PH 544                      // h1/W2 row pitch (bytes): 136w, mod32=8
#define SW2   0                     // 256 rows x PH = 139264
#define SA1   139264                // 64 rows x PA = 10240
#define SH1   149504                // 64 rows x PH = 34816
#define SW3   184320                // 256 f32
#define SB2   185344                // 256 f32
#define SRED  186368                // 8 warps x 64 px f32 = 2048
#define SMEM_TOTAL 188416

__global__ __launch_bounds__(256, 1)
void mlp_mma(const float* __restrict__ edge, const float* __restrict__ b2,
             const float* __restrict__ W3, const float* __restrict__ b3,
             float* __restrict__ out) {
    extern __shared__ char smem[];
    const int tid = threadIdx.x;
    const int wid = tid >> 5, lane = tid & 31;
    const int g = lane >> 2, t4 = lane & 3;

    // stage full W2 (fp16 interleaved rows) + W3/b2
    for (int i = tid; i < 8192; i += 256) {        // hp(8b) * 32 + c(5b)
        int hp = i >> 5, c = i & 31;
        *(uint4*)(smem + SW2 + hp * PH + c * 16) =
            ((const uint4*)(g_W2h + hp * 256))[c];
    }
    ((float*)(smem + SW3))[tid] = W3[tid];
    ((float*)(smem + SB2))[tid] = b2[tid];

    const float* w3s = (const float*)(smem + SW3);
    const float* b2s = (const float*)(smem + SB2);
    float* red = (float*)(smem + SRED);
    const float b3v = b3[0];
    const int hb1 = wid * 32;   // GEMM1: 32 h per warp (ni=4)
    const int hb2 = wid * 32;   // GEMM2: 32 h' per warp (ni=4)
    const int spx = tid & 63, sq = tid >> 6;       // staging: 4 e-blocks of 16

    // prologue: stage first edge tile (fp16, interleaved)
    {
        int t0 = blockIdx.x;
        int mt = t0 & 3, n = (t0 >> 2) & 255, b = t0 >> 10;
        const float* ep = edge +
            ((size_t)(b * 64 + sq * 16) * 256 + n) * 256 + mt * 64 + spx;
        float v[16];
#pragma unroll
        for (int j = 0; j < 16; j++) v[j] = ep[(size_t)j * 65536];
        unsigned w[8];
        w[0]=h2pack(v[0],v[1]);  w[1]=h2pack(v[8],v[9]);
        w[2]=h2pack(v[2],v[3]);  w[3]=h2pack(v[10],v[11]);
        w[4]=h2pack(v[4],v[5]);  w[5]=h2pack(v[12],v[13]);
        w[6]=h2pack(v[6],v[7]);  w[7]=h2pack(v[14],v[15]);
        uint4* dst = (uint4*)(smem + SA1 + spx * PA + sq * 32);
        dst[0] = make_uint4(w[0], w[1], w[2], w[3]);
        dst[1] = make_uint4(w[4], w[5], w[6], w[7]);
    }
    __syncthreads();

    for (int t = blockIdx.x; t < 4096; t += 148) {
        const int mt = t & 3, n = (t >> 2) & 255, b = t >> 10;
        const int m0 = mt * 64;

        float2 Rv[4];
        {
            const float* Rb = g_R + ((b * 256 + n) << 8);
#pragma unroll
            for (int ni = 0; ni < 4; ni++)
                Rv[ni] = *(const float2*)(Rb + hb1 + ni * 8 + 2 * t4);
        }

        // ---- GEMM1: D1[64px, 32h/warp] = A1 x W1e^T, K=64 (4 k16) ----
        float acc1[4][4][4];
#pragma unroll
        for (int mi = 0; mi < 4; mi++)
#pragma unroll
            for (int ni = 0; ni < 4; ni++)
#pragma unroll
                for (int q = 0; q < 4; q++) acc1[mi][ni][q] = 0.f;

#pragma unroll
        for (int kc = 0; kc < 4; kc++) {
            uint2 ar0[4], ar1[4];
#pragma unroll
            for (int mi = 0; mi < 4; mi++) {
                ar0[mi] = *(uint2*)(smem + SA1 + (mi * 16 + g) * PA + kc * 32 + t4 * 8);
                ar1[mi] = *(uint2*)(smem + SA1 + (mi * 16 + g + 8) * PA + kc * 32 + t4 * 8);
            }
#pragma unroll
            for (int ni = 0; ni < 4; ni++) {
                uint2 bb = g_W1p[(hb1 + ni * 8 + g) * 16 + kc * 4 + t4];
#pragma unroll
                for (int mi = 0; mi < 4; mi++)
                    mma_f16(acc1[mi][ni], ar0[mi].x, ar1[mi].x, ar0[mi].y, ar1[mi].y,
                            bb.x, bb.y);
            }
        }

        // ---- epilogue 1: relu(D1 + R + C) -> h1 (fp16, interleaved) ----
        {
            const float* Cb = g_C + ((size_t)(b * 256 + m0) << 8);
#pragma unroll
            for (int mi = 0; mi < 4; mi++)
#pragma unroll
                for (int ni = 0; ni < 4; ni++) {
                    int h = hb1 + ni * 8 + 2 * t4;
                    int px0 = mi * 16 + g, px1 = px0 + 8;
                    float2 C0 = *(const float2*)(Cb + (px0 << 8) + h);
                    float2 C1 = *(const float2*)(Cb + (px1 << 8) + h);
                    float v00 = fmaxf(acc1[mi][ni][0] + Rv[ni].x + C0.x, 0.f);
                    float v01 = fmaxf(acc1[mi][ni][1] + Rv[ni].y + C0.y, 0.f);
                    float v10 = fmaxf(acc1[mi][ni][2] + Rv[ni].x + C1.x, 0.f);
                    float v11 = fmaxf(acc1[mi][ni][3] + Rv[ni].y + C1.y, 0.f);
                    int kcb = h >> 4, p = (h >> 1) & 7;
                    int word = ((p & 3) << 1) | (p >> 2);
                    unsigned off = kcb * 32 + word * 4;
                    *(unsigned*)(smem + SH1 + px0 * PH + off) = h2pack(v00, v01);
                    *(unsigned*)(smem + SH1 + px1 * PH + off) = h2pack(v10, v11);
                }
        }
        __syncthreads();   // h1 visible; A tile free for re-staging

        // ---- prefetch next tile's edge into registers ----
        float ev[16];
        const int tn = t + 148;
        if (tn < 4096) {
            int mtn = tn & 3, nn = (tn >> 2) & 255, bn = tn >> 10;
            const float* ep = edge +
                ((size_t)(bn * 64 + sq * 16) * 256 + nn) * 256 + mtn * 64 + spx;
#pragma unroll
            for (int j = 0; j < 16; j++) ev[j] = ep[(size_t)j * 65536];
        }

        // ---- GEMM2: D2[64px, 32h'/warp] = h1 x W2^T, K=256 (16 k16) ----
        float acc2[4][4][4];
#pragma unroll
        for (int mi = 0; mi < 4; mi++)
#pragma unroll
            for (int ni = 0; ni < 4; ni++)
#pragma unroll
                for (int q = 0; q < 4; q++) acc2[mi][ni][q] = 0.f;

#pragma unroll 2
        for (int kc = 0; kc < 16; kc++) {
            uint2 ar0[4], ar1[4];
#pragma unroll
            for (int mi = 0; mi < 4; mi++) {
                ar0[mi] = *(uint2*)(smem + SH1 + (mi * 16 + g) * PH + kc * 32 + t4 * 8);
                ar1[mi] = *(uint2*)(smem + SH1 + (mi * 16 + g + 8) * PH + kc * 32 + t4 * 8);
            }
#pragma unroll
            for (int ni = 0; ni < 4; ni++) {
                uint2 wb = *(uint2*)(smem + SW2 + (hb2 + ni * 8 + g) * PH + kc * 32 + t4 * 8);
#pragma unroll
                for (int mi = 0; mi < 4; mi++)
                    mma_f16(acc2[mi][ni], ar0[mi].x, ar1[mi].x, ar0[mi].y, ar1[mi].y,
                            wb.x, wb.y);
            }
        }

        // ---- epilogue 2 + layer 3: per-warp partials -> smem ----
        {
            float po[4][2];
#pragma unroll
            for (int mi = 0; mi < 4; mi++) { po[mi][0] = 0.f; po[mi][1] = 0.f; }
#pragma unroll
            for (int mi = 0; mi < 4; mi++)
#pragma unroll
                for (int ni = 0; ni < 4; ni++) {
                    int h = hb2 + ni * 8 + 2 * t4;
                    float w3a = w3s[h], w3b = w3s[h + 1];
                    float ba = b2s[h], bbv = b2s[h + 1];
                    po[mi][0] = fmaf(w3a, fmaxf(acc2[mi][ni][0] + ba, 0.f), po[mi][0]);
                    po[mi][0] = fmaf(w3b, fmaxf(acc2[mi][ni][1] + bbv, 0.f), po[mi][0]);
                    po[mi][1] = fmaf(w3a, fmaxf(acc2[mi][ni][2] + ba, 0.f), po[mi][1]);
                    po[mi][1] = fmaf(w3b, fmaxf(acc2[mi][ni][3] + bbv, 0.f), po[mi][1]);
                }
#pragma unroll
            for (int mi = 0; mi < 4; mi++)
#pragma unroll
                for (int r = 0; r < 2; r++) {
                    po[mi][r] += __shfl_xor_sync(0xffffffffu, po[mi][r], 1);
                    po[mi][r] += __shfl_xor_sync(0xffffffffu, po[mi][r], 2);
                }
            if (t4 == 0) {
#pragma unroll
                for (int mi = 0; mi < 4; mi++) {
                    red[wid * 64 + mi * 16 + g]     = po[mi][0];
                    red[wid * 64 + mi * 16 + g + 8] = po[mi][1];
                }
            }
        }

        // ---- store prefetched edge into the (now free) A buffer ----
        if (tn < 4096) {
            unsigned w[8];
            w[0]=h2pack(ev[0],ev[1]);  w[1]=h2pack(ev[8],ev[9]);
            w[2]=h2pack(ev[2],ev[3]);  w[3]=h2pack(ev[10],ev[11]);
            w[4]=h2pack(ev[4],ev[5]);  w[5]=h2pack(ev[12],ev[13]);
            w[6]=h2pack(ev[6],ev[7]);  w[7]=h2pack(ev[14],ev[15]);
            uint4* dst = (uint4*)(smem + SA1 + spx * PA + sq * 32);
            dst[0] = make_uint4(w[0], w[1], w[2], w[3]);
            dst[1] = make_uint4(w[4], w[5], w[6], w[7]);
        }
        __syncthreads();

        // ---- cross-warp reduce + direct store (tile owned exclusively) ----
        if (tid < 64) {
            float s = b3v;
#pragma unroll
            for (int w = 0; w < 8; w++) s += red[w * 64 + tid];
            out[((b * 256 + n) << 8) + m0 + tid] = s;
        }
        // red is rewritten only after the next iteration's mid-loop sync,
        // so no extra barrier is needed here.
    }
}

extern "C" void kernel_launch(void* const* d_in, const int* in_sizes, int n_in,
                              void* d_out, int out_size) {
    const float* edge = (const float*)d_in[0];
    const float* node = (const float*)d_in[1];
    const float* W1   = (const float*)d_in[2];
    const float* b1   = (const float*)d_in[3];
    const float* W2   = (const float*)d_in[4];
    const float* b2   = (const float*)d_in[5];
    const float* W3   = (const float*)d_in[6];
    const float* b3   = (const float*)d_in[7];
    float* out = (float*)d_out;

    cudaFuncSetAttribute(mlp_mma, cudaFuncAttributeMaxDynamicSharedMemorySize,
                         SMEM_TOTAL);

    prep_all<<<256, 256>>>(W1, W2);
    prep_np<<<1024, 256>>>(node, b1);
    mlp_mma<<<148, 256, SMEM_TOTAL>>>(edge, b2, W3, b3, out);
}

// round 17
// speedup vs baseline: 4.3241x; 1.0063x over previous
#include <cuda_runtime.h>
#include <cuda_fp16.h>

// ---------------------------------------------------------------------------
// B=4, N=256, E=64, C=128, H=256.
// out[b,n,m] = W3.relu(W2.relu(W1.concat(edge,row,col)+b1)+b2)+b3
// R[b,n,h] = W1r.node[:,n] + b1 ; C[b,m,h] = W1c.node[:,m]
// fp16 m16n8k16 mma, full W2 in SMEM, one CTA per tile. This round:
// C prefetched to regs before GEMM1; epilogue-1 paired STS.64.
// ---------------------------------------------------------------------------

__device__ float g_W1rT[128 * 256];
__device__ float g_W1cT[128 * 256];
__device__ float g_R[4 * 256 * 256];          // + b1 folded
__device__ float g_C[4 * 256 * 256];
__device__ uint2 g_W1p[256 * 16];             // W1e fp16 B-frags [h][kc4][t4]
__device__ __half g_W2h[256 * 256];           // W2 fp16, k-interleaved per 16-block

__constant__ int c_perm16[16] = {0,1,8,9,2,3,10,11,4,5,12,13,6,7,14,15};

// ---------------- helpers --------------------------------------------------
__device__ __forceinline__ void mma_f16(float d[4], unsigned a0, unsigned a1,
                                        unsigned a2, unsigned a3,
                                        unsigned b0, unsigned b1) {
    asm volatile(
        "mma.sync.aligned.m16n8k16.row.col.f32.f16.f16.f32 "
        "{%0,%1,%2,%3}, {%4,%5,%6,%7}, {%8,%9}, {%0,%1,%2,%3};"
        : "+f"(d[0]), "+f"(d[1]), "+f"(d[2]), "+f"(d[3])
        : "r"(a0), "r"(a1), "r"(a2), "r"(a3), "r"(b0), "r"(b1));
}
__device__ __forceinline__ unsigned h2pack(float x, float y) {
    __half2 h = __floats2half2_rn(x, y);
    return *(unsigned*)&h;
}

// ---------------- prep kernels (2 launches) --------------------------------
__global__ void prep_all(const float* __restrict__ W1, const float* __restrict__ W2) {
    int i = blockIdx.x * 256 + threadIdx.x;   // 65536
    {                                          // g_W2h, interleaved
        int h = i >> 8, kk = i & 255;
        int kcb = kk >> 4, j = kk & 15;
        g_W2h[i] = __float2half_rn(W2[h * 256 + kcb * 16 + c_perm16[j]]);
    }
    if (i < 32768) {
        int c = i >> 8, h = i & 255;
        g_W1rT[i] = W1[h * 320 + 64 + c];
        g_W1cT[i] = W1[h * 320 + 192 + c];
    }
    if (i < 4096) {                            // g_W1p B-frags
        int h = i >> 4, r = i & 15;
        int kc = r >> 2, t4 = r & 3, ks = kc * 16 + 2 * t4;
        uint2 v;
        v.x = h2pack(W1[h * 320 + ks], W1[h * 320 + ks + 1]);
        v.y = h2pack(W1[h * 320 + ks + 8], W1[h * 320 + ks + 9]);
        g_W1p[i] = v;
    }
}
__global__ void prep_np(const float* __restrict__ node, const float* __restrict__ b1) {
    int b = blockIdx.x >> 8, p = blockIdx.x & 255;
    int h = threadIdx.x;
    __shared__ float ns[128];
    if (h < 128) ns[h] = node[(b * 128 + h) * 256 + p];
    __syncthreads();
    float r = 0.f, c = 0.f;
#pragma unroll 16
    for (int k = 0; k < 128; k++) {
        float v = ns[k];
        r = fmaf(g_W1rT[k * 256 + h], v, r);
        c = fmaf(g_W1cT[k * 256 + h], v, c);
    }
    int o = (b * 256 + p) * 256 + h;
    g_R[o] = r + b1[h];
    g_C[o] = c;
}

// ---------------- main kernel ----------------------------------------------
#define PA 160                      // A row pitch (bytes): 40w, mod32=8
#define PH 544                      // h1/W2 row pitch (bytes): 136w, mod32=8
#define SW2   0                     // 256 rows x PH = 139264
#define SA1   139264                // 64 rows x PA = 10240
#define SH1   149504                // 64 rows x PH = 34816
#define SW3   184320                // 256 f32
#define SB2   185344                // 256 f32
#define SRED  186368                // 8 warps x 64 px f32 = 2048
#define SMEM_TOTAL 188416

__global__ __launch_bounds__(256, 1)
void mlp_mma(const float* __restrict__ edge, const float* __restrict__ b2,
             const float* __restrict__ W3, const float* __restrict__ b3,
             float* __restrict__ out) {
    extern __shared__ char smem[];
    const int tid = threadIdx.x;
    const int wid = tid >> 5, lane = tid & 31;
    const int g = lane >> 2, t4 = lane & 3;

    // stage full W2 (fp16 interleaved rows) + W3/b2
    for (int i = tid; i < 8192; i += 256) {        // hp(8b) * 32 + c(5b)
        int hp = i >> 5, c = i & 31;
        *(uint4*)(smem + SW2 + hp * PH + c * 16) =
            ((const uint4*)(g_W2h + hp * 256))[c];
    }
    ((float*)(smem + SW3))[tid] = W3[tid];
    ((float*)(smem + SB2))[tid] = b2[tid];

    const float* w3s = (const float*)(smem + SW3);
    const float* b2s = (const float*)(smem + SB2);
    float* red = (float*)(smem + SRED);
    const float b3v = b3[0];
    const int hb1 = wid * 32;   // GEMM1: 32 h per warp (ni=4)
    const int hb2 = wid * 32;   // GEMM2: 32 h' per warp (ni=4)
    const int spx = tid & 63, sq = tid >> 6;       // staging: 4 e-blocks of 16

    // prologue: stage first edge tile (fp16, interleaved)
    {
        int t0 = blockIdx.x;
        int mt = t0 & 3, n = (t0 >> 2) & 255, b = t0 >> 10;
        const float* ep = edge +
            ((size_t)(b * 64 + sq * 16) * 256 + n) * 256 + mt * 64 + spx;
        float v[16];
#pragma unroll
        for (int j = 0; j < 16; j++) v[j] = ep[(size_t)j * 65536];
        unsigned w[8];
        w[0]=h2pack(v[0],v[1]);  w[1]=h2pack(v[8],v[9]);
        w[2]=h2pack(v[2],v[3]);  w[3]=h2pack(v[10],v[11]);
        w[4]=h2pack(v[4],v[5]);  w[5]=h2pack(v[12],v[13]);
        w[6]=h2pack(v[6],v[7]);  w[7]=h2pack(v[14],v[15]);
        uint4* dst = (uint4*)(smem + SA1 + spx * PA + sq * 32);
        dst[0] = make_uint4(w[0], w[1], w[2], w[3]);
        dst[1] = make_uint4(w[4], w[5], w[6], w[7]);
    }
    __syncthreads();

    for (int t = blockIdx.x; t < 4096; t += 148) {
        const int mt = t & 3, n = (t >> 2) & 255, b = t >> 10;
        const int m0 = mt * 64;

        // ---- prefetch R and ALL C values into registers (hidden by GEMM1) --
        float2 Rv[4];
        float2 Cv[4][4][2];
        {
            const float* Rb = g_R + ((b * 256 + n) << 8);
            const float* Cb = g_C + ((size_t)(b * 256 + m0) << 8);
#pragma unroll
            for (int ni = 0; ni < 4; ni++) {
                int h = hb1 + ni * 8 + 2 * t4;
                Rv[ni] = *(const float2*)(Rb + h);
#pragma unroll
                for (int mi = 0; mi < 4; mi++) {
                    Cv[mi][ni][0] = *(const float2*)(Cb + ((mi * 16 + g) << 8) + h);
                    Cv[mi][ni][1] = *(const float2*)(Cb + ((mi * 16 + g + 8) << 8) + h);
                }
            }
        }

        // ---- GEMM1: D1[64px, 32h/warp] = A1 x W1e^T, K=64 (4 k16) ----
        float acc1[4][4][4];
#pragma unroll
        for (int mi = 0; mi < 4; mi++)
#pragma unroll
            for (int ni = 0; ni < 4; ni++)
#pragma unroll
                for (int q = 0; q < 4; q++) acc1[mi][ni][q] = 0.f;

#pragma unroll
        for (int kc = 0; kc < 4; kc++) {
            uint2 ar0[4], ar1[4];
#pragma unroll
            for (int mi = 0; mi < 4; mi++) {
                ar0[mi] = *(uint2*)(smem + SA1 + (mi * 16 + g) * PA + kc * 32 + t4 * 8);
                ar1[mi] = *(uint2*)(smem + SA1 + (mi * 16 + g + 8) * PA + kc * 32 + t4 * 8);
            }
#pragma unroll
            for (int ni = 0; ni < 4; ni++) {
                uint2 bb = g_W1p[(hb1 + ni * 8 + g) * 16 + kc * 4 + t4];
#pragma unroll
                for (int mi = 0; mi < 4; mi++)
                    mma_f16(acc1[mi][ni], ar0[mi].x, ar1[mi].x, ar0[mi].y, ar1[mi].y,
                            bb.x, bb.y);
            }
        }

        // ---- epilogue 1: relu(D1 + R + C) -> h1, paired STS.64 ----
        // For ni even/odd pair: offsets kcb*32 + t4*8 and +4 -> one uint2.
        {
#pragma unroll
            for (int mi = 0; mi < 4; mi++) {
                int px0 = mi * 16 + g, px1 = px0 + 8;
#pragma unroll
                for (int np = 0; np < 2; np++) {     // ni = 2*np, 2*np+1
                    int nie = 2 * np, nio = nie + 1;
                    float e00 = fmaxf(acc1[mi][nie][0] + Rv[nie].x + Cv[mi][nie][0].x, 0.f);
                    float e01 = fmaxf(acc1[mi][nie][1] + Rv[nie].y + Cv[mi][nie][0].y, 0.f);
                    float e10 = fmaxf(acc1[mi][nie][2] + Rv[nie].x + Cv[mi][nie][1].x, 0.f);
                    float e11 = fmaxf(acc1[mi][nie][3] + Rv[nie].y + Cv[mi][nie][1].y, 0.f);
                    float o00 = fmaxf(acc1[mi][nio][0] + Rv[nio].x + Cv[mi][nio][0].x, 0.f);
                    float o01 = fmaxf(acc1[mi][nio][1] + Rv[nio].y + Cv[mi][nio][0].y, 0.f);
                    float o10 = fmaxf(acc1[mi][nio][2] + Rv[nio].x + Cv[mi][nio][1].x, 0.f);
                    float o11 = fmaxf(acc1[mi][nio][3] + Rv[nio].y + Cv[mi][nio][1].y, 0.f);
                    unsigned off = (2 * wid + np) * 32 + t4 * 8;
                    *(uint2*)(smem + SH1 + px0 * PH + off) =
                        make_uint2(h2pack(e00, e01), h2pack(o00, o01));
                    *(uint2*)(smem + SH1 + px1 * PH + off) =
                        make_uint2(h2pack(e10, e11), h2pack(o10, o11));
                }
            }
        }
        __syncthreads();   // h1 visible; A tile free for re-staging

        // ---- prefetch next tile's edge into registers ----
        float ev[16];
        const int tn = t + 148;
        if (tn < 4096) {
            int mtn = tn & 3, nn = (tn >> 2) & 255, bn = tn >> 10;
            const float* ep = edge +
                ((size_t)(bn * 64 + sq * 16) * 256 + nn) * 256 + mtn * 64 + spx;
#pragma unroll
            for (int j = 0; j < 16; j++) ev[j] = ep[(size_t)j * 65536];
        }

        // ---- GEMM2: D2[64px, 32h'/warp] = h1 x W2^T, K=256 (16 k16) ----
        float acc2[4][4][4];
#pragma unroll
        for (int mi = 0; mi < 4; mi++)
#pragma unroll
            for (int ni = 0; ni < 4; ni++)
#pragma unroll
                for (int q = 0; q < 4; q++) acc2[mi][ni][q] = 0.f;

#pragma unroll 2
        for (int kc = 0; kc < 16; kc++) {
            uint2 ar0[4], ar1[4];
#pragma unroll
            for (int mi = 0; mi < 4; mi++) {
                ar0[mi] = *(uint2*)(smem + SH1 + (mi * 16 + g) * PH + kc * 32 + t4 * 8);
                ar1[mi] = *(uint2*)(smem + SH1 + (mi * 16 + g + 8) * PH + kc * 32 + t4 * 8);
            }
#pragma unroll
            for (int ni = 0; ni < 4; ni++) {
                uint2 wb = *(uint2*)(smem + SW2 + (hb2 + ni * 8 + g) * PH + kc * 32 + t4 * 8);
#pragma unroll
                for (int mi = 0; mi < 4; mi++)
                    mma_f16(acc2[mi][ni], ar0[mi].x, ar1[mi].x, ar0[mi].y, ar1[mi].y,
                            wb.x, wb.y);
            }
        }

        // ---- epilogue 2 + layer 3: per-warp partials -> smem ----
        {
            float po[4][2];
#pragma unroll
            for (int mi = 0; mi < 4; mi++) { po[mi][0] = 0.f; po[mi][1] = 0.f; }
#pragma unroll
            for (int mi = 0; mi < 4; mi++)
#pragma unroll
                for (int ni = 0; ni < 4; ni++) {
                    int h = hb2 + ni * 8 + 2 * t4;
                    float w3a = w3s[h], w3b = w3s[h + 1];
                    float ba = b2s[h], bbv = b2s[h + 1];
                    po[mi][0] = fmaf(w3a, fmaxf(acc2[mi][ni][0] + ba, 0.f), po[mi][0]);
                    po[mi][0] = fmaf(w3b, fmaxf(acc2[mi][ni][1] + bbv, 0.f), po[mi][0]);
                    po[mi][1] = fmaf(w3a, fmaxf(acc2[mi][ni][2] + ba, 0.f), po[mi][1]);
                    po[mi][1] = fmaf(w3b, fmaxf(acc2[mi][ni][3] + bbv, 0.f), po[mi][1]);
                }
#pragma unroll
            for (int mi = 0; mi < 4; mi++)
#pragma unroll
                for (int r = 0; r < 2; r++) {
                    po[mi][r] += __shfl_xor_sync(0xffffffffu, po[mi][r], 1);
                    po[mi][r] += __shfl_xor_sync(0xffffffffu, po[mi][r], 2);
                }
            if (t4 == 0) {
#pragma unroll
                for (int mi = 0; mi < 4; mi++) {
                    red[wid * 64 + mi * 16 + g]     = po[mi][0];
                    red[wid * 64 + mi * 16 + g + 8] = po[mi][1];
                }
            }
        }

        // ---- store prefetched edge into the (now free) A buffer ----
        if (tn < 4096) {
            unsigned w[8];
            w[0]=h2pack(ev[0],ev[1]);  w[1]=h2pack(ev[8],ev[9]);
            w[2]=h2pack(ev[2],ev[3]);  w[3]=h2pack(ev[10],ev[11]);
            w[4]=h2pack(ev[4],ev[5]);  w[5]=h2pack(ev[12],ev[13]);
            w[6]=h2pack(ev[6],ev[7]);  w[7]=h2pack(ev[14],ev[15]);
            uint4* dst = (uint4*)(smem + SA1 + spx * PA + sq * 32);
            dst[0] = make_uint4(w[0], w[1], w[2], w[3]);
            dst[1] = make_uint4(w[4], w[5], w[6], w[7]);
        }
        __syncthreads();

        // ---- cross-warp reduce + direct store (tile owned exclusively) ----
        if (tid < 64) {
            float s = b3v;
#pragma unroll
            for (int w = 0; w < 8; w++) s += red[w * 64 + tid];
            out[((b * 256 + n) << 8) + m0 + tid] = s;
        }
        // red is rewritten only after the next iteration's mid-loop sync.
    }
}

extern "C" void kernel_launch(void* const* d_in, const int* in_sizes, int n_in,
                              void* d_out, int out_size) {
    const float* edge = (const float*)d_in[0];
    const float* node = (const float*)d_in[1];
    const float* W1   = (const float*)d_in[2];
    const float* b1   = (const float*)d_in[3];
    const float* W2   = (const float*)d_in[4];
    const float* b2   = (const float*)d_in[5];
    const float* W3   = (const float*)d_in[6];
    const float* b3   = (const float*)d_in[7];
    float* out = (float*)d_out;

    cudaFuncSetAttribute(mlp_mma, cudaFuncAttributeMaxDynamicSharedMemorySize,
                         SMEM_TOTAL);

    prep_all<<<256, 256>>>(W1, W2);
    prep_np<<<1024, 256>>>(node, b1);
    mlp_mma<<<148, 256, SMEM_TOTAL>>>(edge, b2, W3, b3, out);
}